// round 13
// baseline (speedup 1.0000x reference)
#include <cuda_runtime.h>

// Split formulation of lp[r,p] = sum_f w[p,f]^2 * sum_e x[r,f,e]^2
//
// Kernel 1 (streaming, HBM-bound): xsq[r,f] = sum_e x[r,f,e]^2
//   Warp-per-row, 8 float4 loads up front, quad butterfly for the e-sum,
//   8 scalar stores (L2-targeted). Tail per row is ~3x smaller than the
//   fused kernel's -> load duty ~88% (vs the ~70% duty-cycle pin measured
//   in R4/R6).
//
// Kernel 2 (tiny, L2-resident input): lp[r,p] = sum_f wsq[p,f] * xsq[r,f]
//   128-row smem tile per block, thread-per-row, weights broadcast from smem.
//
// x: [R=32768, F=64, E=16] fp32; w: [10, 64] fp32; out: [R, 10] fp32.

#define R_ROWS 32768
#define F_DIM 64
#define E_DIM 16
#define P_DIM 10

#define K1_THREADS 256
#define K1_BLOCKS 740   // 5 blocks/SM * 148 SMs; grid-stride over rows

#define TILE_R 128      // kernel2 rows per block
#define XPAD 68         // padded row stride in floats (4-phase LDS floor)

__device__ float g_xsq[R_ROWS * F_DIM];   // 8.4 MB scratch

// ---------------------------------------------------------------- kernel 1
__global__ __launch_bounds__(K1_THREADS, 5) void xsq_kernel(
    const float* __restrict__ x)
{
    const int lane = threadIdx.x & 31;
    const int q = lane >> 2;   // f sub-index within a step
    const int c = lane & 3;    // e-quarter
    const int warp = threadIdx.x >> 5;
    const int gwarp = blockIdx.x * (K1_THREADS / 32) + warp;
    const int nwarp = K1_BLOCKS * (K1_THREADS / 32);

    for (int r = gwarp; r < R_ROWS; r += nwarp) {
        const float4* __restrict__ xr =
            reinterpret_cast<const float4*>(x + (size_t)r * (F_DIM * E_DIM));

        // 8-deep load batch (32 regs for v[]), streaming hint.
        float4 v[8];
#pragma unroll
        for (int j = 0; j < 8; ++j) {
            v[j] = __ldcs(&xr[j * 32 + lane]);
        }

        float* xo = &g_xsq[(size_t)r * F_DIM];
#pragma unroll
        for (int j = 0; j < 8; ++j) {
            float4 a = v[j];
            float s = fmaf(a.x, a.x,
                      fmaf(a.y, a.y,
                      fmaf(a.z, a.z, a.w * a.w)));
            // sum over e: 16 values span the 4 lanes of the quad
            s += __shfl_xor_sync(0xFFFFFFFFu, s, 1);
            s += __shfl_xor_sync(0xFFFFFFFFu, s, 2);
            if (c == 0) {
                // lanes 0,4,...,28 -> f = 8j+0..8j+7: 32B contiguous burst.
                // __stcg: land in L2 (kernel 2 reads it back through L2).
                __stcg(&xo[8 * j + q], s);
            }
        }
    }
}

// ---------------------------------------------------------------- kernel 2
__global__ __launch_bounds__(TILE_R) void lp_kernel(
    const float* __restrict__ w,
    float* __restrict__ out)
{
    __shared__ float sx[TILE_R * XPAD];      // 34.8 KB
    __shared__ float swsq[P_DIM * F_DIM];    // 2.5 KB, [p][f]

    const int t = threadIdx.x;

    for (int i = t; i < P_DIM * F_DIM; i += TILE_R) {
        float v = w[i];
        swsq[i] = v * v;
    }

    // Stage 128 rows of xsq (2048 float4s) densely; padded smem rows.
    const float4* gx = reinterpret_cast<const float4*>(g_xsq)
                     + (size_t)blockIdx.x * TILE_R * (F_DIM / 4);
#pragma unroll
    for (int k = 0; k < 16; ++k) {
        int idx = k * TILE_R + t;            // 0..2047
        int row = idx >> 4;
        int col = idx & 15;
        float4 a = __ldcg(&gx[idx]);         // L2 hit expected
        *reinterpret_cast<float4*>(&sx[row * XPAD + col * 4]) = a;
    }
    __syncthreads();

    // Thread t computes row t: 10 accumulators over 64 f's.
    float acc[P_DIM];
#pragma unroll
    for (int p = 0; p < P_DIM; ++p) acc[p] = 0.0f;

#pragma unroll
    for (int fc = 0; fc < 4; ++fc) {
        float xv[16];
#pragma unroll
        for (int u = 0; u < 4; ++u) {
            float4 a = *reinterpret_cast<const float4*>(
                &sx[t * XPAD + fc * 16 + 4 * u]);
            xv[4 * u + 0] = a.x; xv[4 * u + 1] = a.y;
            xv[4 * u + 2] = a.z; xv[4 * u + 3] = a.w;
        }
#pragma unroll
        for (int p = 0; p < P_DIM; ++p) {
            const float* wr = &swsq[p * F_DIM + fc * 16];
            float a0 = acc[p];
#pragma unroll
            for (int u = 0; u < 16; ++u) {
                a0 = fmaf(xv[u], wr[u], a0);   // weight LDS is warp-uniform
            }
            acc[p] = a0;
        }
    }

    const int r = blockIdx.x * TILE_R + t;
    float* o = out + (size_t)r * P_DIM;
#pragma unroll
    for (int p = 0; p < P_DIM; ++p) o[p] = acc[p];
}

// ---------------------------------------------------------------- launch
extern "C" void kernel_launch(void* const* d_in, const int* in_sizes, int n_in,
                              void* d_out, int out_size)
{
    const float* x = (const float*)d_in[0];   // [32768, 64, 16]
    const float* w = (const float*)d_in[1];   // [10, 64]
    float* out = (float*)d_out;               // [32768, 10]
    (void)in_sizes; (void)n_in; (void)out_size;

    xsq_kernel<<<K1_BLOCKS, K1_THREADS>>>(x);
    lp_kernel<<<R_ROWS / TILE_R, TILE_R>>>(w, out);
}

// round 14
// speedup vs baseline: 1.0010x; 1.0010x over previous
#include <cuda_runtime.h>

// Split formulation of lp[r,p] = sum_f w[p,f]^2 * sum_e x[r,f,e]^2
//
// Kernel 1 (streaming, HBM-bound, MEASURED ~20.3us @ prediction): unchanged.
// Kernel 2 (rebuilt): 4 threads per row (quad lane c owns f in
//   [16c, 16c+16)), 512 blocks x 256 threads = 131K threads (~28 warps/SM,
//   4x the R13 parallelism that caused occ=10%). xsq read directly from L2
//   (__ldcg, no smem staging); squared weights in smem as float4 with
//   5-float4 c-stride -> conflict-free LDS.128 (40/thread vs 160 scalar).
//   Quad butterfly (xor 1,2) completes the f-sum; lane c stores p in
//   {c, c+4, c+8<10}.
//
// x: [R=32768, F=64, E=16] fp32; w: [10, 64] fp32; out: [R, 10] fp32.

#define R_ROWS 32768
#define F_DIM 64
#define E_DIM 16
#define P_DIM 10

#define K1_THREADS 256
#define K1_BLOCKS 740   // 5 blocks/SM * 148 SMs; grid-stride over rows

#define K2_THREADS 256
#define K2_BLOCKS (R_ROWS * 4 / K2_THREADS)   // 512

__device__ float g_xsq[R_ROWS * F_DIM];   // 8.4 MB scratch

// ---------------------------------------------------------------- kernel 1
__global__ __launch_bounds__(K1_THREADS, 5) void xsq_kernel(
    const float* __restrict__ x)
{
    const int lane = threadIdx.x & 31;
    const int q = lane >> 2;   // f sub-index within a step
    const int c = lane & 3;    // e-quarter
    const int warp = threadIdx.x >> 5;
    const int gwarp = blockIdx.x * (K1_THREADS / 32) + warp;
    const int nwarp = K1_BLOCKS * (K1_THREADS / 32);

    for (int r = gwarp; r < R_ROWS; r += nwarp) {
        const float4* __restrict__ xr =
            reinterpret_cast<const float4*>(x + (size_t)r * (F_DIM * E_DIM));

        // 8-deep load batch (32 regs for v[]), streaming hint.
        float4 v[8];
#pragma unroll
        for (int j = 0; j < 8; ++j) {
            v[j] = __ldcs(&xr[j * 32 + lane]);
        }

        float* xo = &g_xsq[(size_t)r * F_DIM];
#pragma unroll
        for (int j = 0; j < 8; ++j) {
            float4 a = v[j];
            float s = fmaf(a.x, a.x,
                      fmaf(a.y, a.y,
                      fmaf(a.z, a.z, a.w * a.w)));
            // sum over e: 16 values span the 4 lanes of the quad
            s += __shfl_xor_sync(0xFFFFFFFFu, s, 1);
            s += __shfl_xor_sync(0xFFFFFFFFu, s, 2);
            if (c == 0) {
                // lanes 0,4,...,28 -> f = 8j+0..8j+7: 32B contiguous burst.
                __stcg(&xo[8 * j + q], s);
            }
        }
    }
}

// ---------------------------------------------------------------- kernel 2
// swv[(p*4 + c)*5 + v] = float4 of wsq[p][c*16 + 4v .. c*16 + 4v + 3]
// (v-dim padded 4->5 float4s: bank-quad base 20c mod 32 = {0,20,8,28},
//  conflict-free LDS.128 across the warp; same-(c) lanes broadcast.)
__global__ __launch_bounds__(K2_THREADS) void lp_kernel(
    const float* __restrict__ w,
    float* __restrict__ out)
{
    __shared__ float4 swv[P_DIM * 4 * 5];    // 3.2 KB

    const int t = threadIdx.x;

    if (t < P_DIM * 16) {                    // 160 float4s
        const int p = t >> 4;
        const int cw = (t >> 2) & 3;
        const int v = t & 3;
        const float* ws = &w[p * F_DIM + cw * 16 + 4 * v];
        float4 q;
        q.x = ws[0] * ws[0];
        q.y = ws[1] * ws[1];
        q.z = ws[2] * ws[2];
        q.w = ws[3] * ws[3];
        swv[(p * 4 + cw) * 5 + v] = q;
    }
    __syncthreads();

    const int g = blockIdx.x * K2_THREADS + t;
    const int row = g >> 2;
    const int c = g & 3;                     // f-chunk owner (== lane&3)

    // Load this thread's 16 xsq values (f = 16c .. 16c+15) from L2.
    const float4* gx = reinterpret_cast<const float4*>(g_xsq)
                     + (size_t)row * (F_DIM / 4) + c * 4;
    float4 xv[4];
#pragma unroll
    for (int u = 0; u < 4; ++u) {
        xv[u] = __ldcg(&gx[u]);
    }

    float acc[P_DIM];
#pragma unroll
    for (int p = 0; p < P_DIM; ++p) acc[p] = 0.0f;

#pragma unroll
    for (int p = 0; p < P_DIM; ++p) {
        const float4* wp = &swv[(p * 4 + c) * 5];
        float a0 = 0.0f;
#pragma unroll
        for (int v = 0; v < 4; ++v) {
            float4 wq = wp[v];
            float4 xq = xv[v];
            a0 = fmaf(xq.x, wq.x, a0);
            a0 = fmaf(xq.y, wq.y, a0);
            a0 = fmaf(xq.z, wq.z, a0);
            a0 = fmaf(xq.w, wq.w, a0);
        }
        acc[p] = a0;
    }

    // Sum the 4 f-chunks across the quad; every lane ends with full sums.
#pragma unroll
    for (int p = 0; p < P_DIM; ++p) {
        acc[p] += __shfl_xor_sync(0xFFFFFFFFu, acc[p], 1);
        acc[p] += __shfl_xor_sync(0xFFFFFFFFu, acc[p], 2);
    }

    // Lane c stores p = c, c+4, and c+8 (if < 10): 10 contiguous floats/quad.
    float r0 = (c == 0) ? acc[0] : (c == 1) ? acc[1] : (c == 2) ? acc[2] : acc[3];
    float r1 = (c == 0) ? acc[4] : (c == 1) ? acc[5] : (c == 2) ? acc[6] : acc[7];
    float r2 = (c == 0) ? acc[8] : acc[9];

    float* o = out + (size_t)row * P_DIM;
    o[c] = r0;
    o[4 + c] = r1;
    if (c < 2) o[8 + c] = r2;
}

// ---------------------------------------------------------------- launch
extern "C" void kernel_launch(void* const* d_in, const int* in_sizes, int n_in,
                              void* d_out, int out_size)
{
    const float* x = (const float*)d_in[0];   // [32768, 64, 16]
    const float* w = (const float*)d_in[1];   // [10, 64]
    float* out = (float*)d_out;               // [32768, 10]
    (void)in_sizes; (void)n_in; (void)out_size;

    xsq_kernel<<<K1_BLOCKS, K1_THREADS>>>(x);
    lp_kernel<<<K2_BLOCKS, K2_THREADS>>>(w, out);
}